// round 14
// baseline (speedup 1.0000x reference)
#include <cuda_runtime.h>

// ChamferDistance: B=8, N=M=8192, D=3.
// d(i,j) = n_j + (-2y_j).x_i + |x_i|^2 ; min over j per i (both directions).
// Interleaved tiles (two opposing points pair-packed per 32B entry, -2 folded
// in -> 0.25 LDS.128 per pair) + low-register owned-broadcast (RX=4, ~48 regs)
// -> high occupancy AND low L1 port pressure. 1024 blocks, single launch.

#define TPB     256
#define RX      4
#define CHUNK   (TPB * RX)          // 1024 owned points per group
#define PTS     8192
#define BATCH   8
#define NCHUNK  (PTS / CHUNK)       // 8
#define NJS     8                   // j-slices per group
#define JSEG    (PTS / NJS)         // 1024 opposing points per block
#define TILE    JSEG
#define JP      (TILE / 2)          // 512 j-pairs per tile
#define NGROUP  (2 * BATCH * NCHUNK)    // 128
#define NBLOCKS (NGROUP * NJS)          // 1024

__device__ float    g_pmin[NGROUP * NJS * CHUNK];   // 4.2 MB scratch
__device__ float    g_part[NGROUP];
__device__ unsigned g_gticket[NGROUP];
__device__ unsigned g_fticket;

#define PACK_F32X2(out, lo, hi) \
    asm("mov.b64 %0, {%1, %2};" : "=l"(out) : "f"(lo), "f"(hi))

#define UNPACK_F32X2(lo, hi, in) \
    asm("mov.b64 {%0, %1}, %2;" : "=f"(lo), "=f"(hi) : "l"(in))

#define FMA_F32X2(d, a, b, c) \
    asm("fma.rn.f32x2 %0, %1, %2, %3;" : "=l"(d) : "l"(a), "l"(b), "l"(c))

__global__ __launch_bounds__(TPB)
void chamfer_pass_kernel(const float* __restrict__ x, const float* __restrict__ y,
                         float* __restrict__ out) {
    const int bid   = blockIdx.x;
    const int dir   = bid >> 9;                 // 0..1
    const int batch = (bid >> 6) & 7;           // 0..7
    const int chunk = (bid >> 3) & 7;           // 0..7
    const int js    = bid & 7;                  // 0..7
    const int group = (dir * BATCH + batch) * NCHUNK + chunk;   // 0..127

    const float* __restrict__ ownb = (dir ? y : x) + (size_t)batch * PTS * 3;
    const float* __restrict__ oppb = (dir ? x : y) + (size_t)batch * PTS * 3;

    // Per j-pair: sAB = {(-2a0,-2a1),(-2b0,-2b1)}, sCN = {(-2c0,-2c1),(n0,n1)}
    __shared__ __align__(16) ulonglong2 sAB[JP];
    __shared__ __align__(16) ulonglong2 sCN[JP];

    const int tid = threadIdx.x;

    // Owned points: coordinate broadcast into both f32x2 lanes.
    unsigned long long xa[RX], xb[RX], xc[RX];
    float mnl[RX], mnh[RX];
#pragma unroll
    for (int r = 0; r < RX; r++) {
        int i = chunk * CHUNK + r * TPB + tid;
        float a = ownb[i * 3 + 0];
        float b = ownb[i * 3 + 1];
        float c = ownb[i * 3 + 2];
        PACK_F32X2(xa[r], a, a);
        PACK_F32X2(xb[r], b, b);
        PACK_F32X2(xc[r], c, c);
        mnl[r] = 3.4e38f;
        mnh[r] = 3.4e38f;
    }

    // single tile fill: JSEG == TILE
    {
        const int jbase = js * JSEG;
#pragma unroll
        for (int jj = tid; jj < TILE; jj += TPB) {
            const float* p = oppb + (size_t)(jbase + jj) * 3;
            float a = p[0], b = p[1], c = p[2];
            float n = fmaf(a, a, fmaf(b, b, c * c));
            int jp = jj >> 1, lane = jj & 1;
            float* pab = (float*)&sAB[jp];
            float* pcn = (float*)&sCN[jp];
            pab[lane + 0] = -2.0f * a;
            pab[lane + 2] = -2.0f * b;
            pcn[lane + 0] = -2.0f * c;
            pcn[lane + 2] = n;
        }
        __syncthreads();

#pragma unroll 8
        for (int jp = 0; jp < JP; ++jp) {
            ulonglong2 ab = sAB[jp];   // LDS.128 broadcast: (-2a pair),(-2b pair)
            ulonglong2 cn = sCN[jp];   // LDS.128 broadcast: (-2c pair),(n pair)
#pragma unroll
            for (int r = 0; r < RX; ++r) {
                unsigned long long t;
                FMA_F32X2(t, xc[r], cn.x, cn.y);
                FMA_F32X2(t, xb[r], ab.y, t);
                FMA_F32X2(t, xa[r], ab.x, t);
                float lo, hi;
                UNPACK_F32X2(lo, hi, t);
                mnl[r] = fminf(mnl[r], lo);
                mnh[r] = fminf(mnh[r], hi);
            }
        }
    }

    // publish this j-slice's partial mins
#pragma unroll
    for (int r = 0; r < RX; r++)
        g_pmin[(group * NJS + js) * CHUNK + r * TPB + tid] = fminf(mnl[r], mnh[r]);

    // per-group ticket: 8th arrival combines (fixed order -> deterministic)
    __shared__ bool isComb;
    __threadfence();
    __syncthreads();
    if (tid == 0) {
        unsigned t = atomicAdd(&g_gticket[group], 1u);
        isComb = (t == NJS - 1);
        if (isComb) g_gticket[group] = 0;   // reset for next replay
    }
    __syncthreads();
    if (!isComb) return;
    __threadfence();

    float s = 0.0f;
#pragma unroll
    for (int r = 0; r < RX; r++) {
        int idx = r * TPB + tid;
        float m = 3.4e38f;
#pragma unroll
        for (int ss = 0; ss < NJS; ss++)
            m = fminf(m, g_pmin[(group * NJS + ss) * CHUNK + idx]);
        float a, b, c, d0, d1, d2;
        UNPACK_F32X2(a, d0, xa[r]);   // rename: lane0 = coordinate
        UNPACK_F32X2(b, d1, xb[r]);
        UNPACK_F32X2(c, d2, xc[r]);
        s += m + fmaf(a, a, fmaf(b, b, c * c));
    }

    __shared__ float red[TPB];
    red[tid] = s;
    __syncthreads();
#pragma unroll
    for (int o = TPB / 2; o > 0; o >>= 1) {
        if (tid < o) red[tid] += red[tid + o];
        __syncthreads();
    }
    if (tid == 0) g_part[group] = red[0];

    // global ticket over the 128 combiners: last one reduces the scalar
    __shared__ bool isFin;
    __threadfence();
    __syncthreads();
    if (tid == 0) {
        unsigned t = atomicAdd(&g_fticket, 1u);
        isFin = (t == NGROUP - 1);
        if (isFin) g_fticket = 0;   // reset for next replay
    }
    __syncthreads();
    if (!isFin) return;
    __threadfence();

    float v = (tid < NGROUP) ? g_part[tid] : 0.0f;
    red[tid] = v;
    __syncthreads();
#pragma unroll
    for (int o = TPB / 2; o > 0; o >>= 1) {
        if (tid < o) red[tid] += red[tid + o];
        __syncthreads();
    }
    if (tid == 0) out[0] = red[0] * (1.0f / 65536.0f);
}

extern "C" void kernel_launch(void* const* d_in, const int* in_sizes, int n_in,
                              void* d_out, int out_size) {
    const float* x = (const float*)d_in[0];
    const float* y = (const float*)d_in[1];
    float* out = (float*)d_out;

    chamfer_pass_kernel<<<NBLOCKS, TPB>>>(x, y, out);
}